// round 2
// baseline (speedup 1.0000x reference)
#include <cuda_runtime.h>
#include <cstdint>

// DeltaModulationEncoder: per-row (B*C = 4096 rows) sequential delta-mod scan
// over T = 8192. Bit-exact replication of the reference float arithmetic:
//   d     = x - recon                        (FADD)
//   step  = (|d| > 0.1f) ? copysign(0.1f,d) : 0   (FSETP |d| -> FSEL, signed 0.1f via LOP3)
//   recon = recon + step                     (FADD; step is exactly ±0.1f or 0)
//   net   = step * 10.0f                     (exact: RN(0.1f*10) == 1.0f), off the chain
//
// Lane = row. 128 blocks x 32 threads => 128 warps spread over the SMs.
// Each lane streams its own row: per 32-step iteration it reads exactly one
// 128B line (8x LDG.128), double-buffered one iteration ahead.

#define TT 8192
#define STEPS_PER_ITER 32
#define NITER (TT / STEPS_PER_ITER)   // 256

__global__ void __launch_bounds__(32, 1)
delta_mod_kernel(const float* __restrict__ x, float* __restrict__ out, int rows)
{
    const int row = blockIdx.x * 32 + threadIdx.x;
    if (row >= rows) return;

    const float4* __restrict__ px = reinterpret_cast<const float4*>(x + (size_t)row * TT);
    float4* __restrict__ po       = reinterpret_cast<float4*>(out + (size_t)row * TT);

    const float TH = 0.1f;                    // == jnp.float32(0.1), bits 0x3DCCCCCD
    float recon = 0.0f;

    // double-buffered prefetch: one iteration (8 x float4 = one 128B line) ahead
    float4 buf[8];
#pragma unroll
    for (int j = 0; j < 8; ++j) buf[j] = px[j];

    for (int it = 0; it < NITER; ++it) {
        float4 cur[8];
#pragma unroll
        for (int j = 0; j < 8; ++j) cur[j] = buf[j];

        // prefetch next chunk (clamped on last iter: harmless reload, keeps it branchless)
        const int nx = (it + 1 < NITER) ? (it + 1) : (NITER - 1);
#pragma unroll
        for (int j = 0; j < 8; ++j) buf[j] = px[nx * 8 + j];

        float4 o[8];
#pragma unroll
        for (int j = 0; j < 8; ++j) {
            float xs0 = cur[j].x, xs1 = cur[j].y, xs2 = cur[j].z, xs3 = cur[j].w;
            float n0, n1, n2, n3;

            {
                float d = xs0 - recon;
                float sth = __uint_as_float((__float_as_uint(d) & 0x80000000u) | 0x3DCCCCCDu);
                float step = (fabsf(d) > TH) ? sth : 0.0f;
                recon = recon + step;
                n0 = step * 10.0f;
            }
            {
                float d = xs1 - recon;
                float sth = __uint_as_float((__float_as_uint(d) & 0x80000000u) | 0x3DCCCCCDu);
                float step = (fabsf(d) > TH) ? sth : 0.0f;
                recon = recon + step;
                n1 = step * 10.0f;
            }
            {
                float d = xs2 - recon;
                float sth = __uint_as_float((__float_as_uint(d) & 0x80000000u) | 0x3DCCCCCDu);
                float step = (fabsf(d) > TH) ? sth : 0.0f;
                recon = recon + step;
                n2 = step * 10.0f;
            }
            {
                float d = xs3 - recon;
                float sth = __uint_as_float((__float_as_uint(d) & 0x80000000u) | 0x3DCCCCCDu);
                float step = (fabsf(d) > TH) ? sth : 0.0f;
                recon = recon + step;
                n3 = step * 10.0f;
            }
            o[j] = make_float4(n0, n1, n2, n3);
        }

#pragma unroll
        for (int j = 0; j < 8; ++j) po[it * 8 + j] = o[j];
    }
}

extern "C" void kernel_launch(void* const* d_in, const int* in_sizes, int n_in,
                              void* d_out, int out_size)
{
    const float* x = (const float*)d_in[0];
    float* out = (float*)d_out;

    const int rows = in_sizes[0] / TT;              // 4096 = 16 * 256
    const int blocks = (rows + 31) / 32;            // 128

    delta_mod_kernel<<<blocks, 32>>>(x, out, rows);
}